// round 10
// baseline (speedup 1.0000x reference)
#include <cuda_runtime.h>
#include <cstdint>
#include <mma.h>

using namespace nvcuda;

#define R_DIM 600
#define D_DIM 240
#define N_DIM 840
#define H_DIM 8
#define C_DIM 64
#define HC 512
#define E_DIM 20000
#define ME 20840            // E + N (self loops)
#define F_CNN 1242
#define NEG 0.2f

// padded dims for guard-free GEMM pipelines
#define KP 1248             // 39 * 32
#define NP 1280             // 20 * 64
#define MP 896              // 7 * 128

// ---------------- scratch (device globals; no allocation allowed) ----------
__device__ float g_xl[N_DIM * HC];
__device__ float g_xr[N_DIM * HC];
__device__ float g_logits[ME * H_DIM];
__device__ int   g_offset[N_DIM + 1];
__device__ int   g_csr[ME];
__device__ float g_res[MP * HC];       // GAT output, tf32-rounded; rows 840+ stay 0
__device__ float g_wc[HC * NP];        // expanded conv weights, tf32
__device__ float g_cb[NP];             // expanded conv bias
__device__ float g_cat[MP * NP];       // conv output, padded, tf32-rounded
__device__ float g_wp[KP * NP];        // padded Wfc, tf32
__device__ float g_feat[N_DIM * F_CNN];

// ---------------- cp.async helpers -------------------------------------------
__device__ __forceinline__ void cp16(float* dst_smem, const float* src) {
    unsigned int d = (unsigned int)__cvta_generic_to_shared(dst_smem);
    asm volatile("cp.async.cg.shared.global [%0], [%1], 16;\n" :: "r"(d), "l"(src) : "memory");
}
__device__ __forceinline__ void cp_commit() {
    asm volatile("cp.async.commit_group;\n" ::: "memory");
}
template<int W> __device__ __forceinline__ void cp_wait() {
    asm volatile("cp.async.wait_group %0;\n" :: "n"(W) : "memory");
}

// ---------------- edge helpers ------------------------------------------------
__device__ __forceinline__ int edge_dst(const int* ei, int e) {
    return (e < E_DIM) ? ei[E_DIM + e] : (e - E_DIM);
}
__device__ __forceinline__ int edge_src(const int* ei, int e) {
    return (e < E_DIM) ? ei[e] : (e - E_DIM);
}

// ---------------- pad kernel: Wfc pad, g_cat row pad, labels, WC, cb ---------
__global__ void k_pad(const float* __restrict__ Wfc, const float* __restrict__ rel,
                      float* __restrict__ out, size_t labels_off,
                      const float* __restrict__ c1w, const float* __restrict__ c4w,
                      const float* __restrict__ c16w, const float* __restrict__ c32w,
                      const float* __restrict__ c1b, const float* __restrict__ c4b,
                      const float* __restrict__ c16b, const float* __restrict__ c32b) {
    int idx = blockIdx.x * 256 + threadIdx.x;
    const int T1 = KP * NP;
    const int T2 = T1 + (MP - N_DIM) * NP;
    const int T3 = T2 + R_DIM * D_DIM;
    const int T4 = T3 + HC * NP;
    const int T5 = T4 + NP;
    if (idx < T1) {
        int r = idx / NP, c = idx % NP;
        float v = (r < F_CNN && c < F_CNN) ? Wfc[(size_t)r * F_CNN + c] : 0.f;
        g_wp[idx] = wmma::__float_to_tf32(v);
    } else if (idx < T2) {
        g_cat[(size_t)N_DIM * NP + (idx - T1)] = 0.f;
    } else if (idx < T3) {
        int j = idx - T2;
        out[labels_off + j] = rel[j];
    } else if (idx < T4) {
        int j = idx - T3;
        int c = j / NP, o = j % NP;
        int h = c >> 6, cc = c & 63;
        float v = 0.f;
        if (o < 384)       { int oc = o >> 6, p = o & 63;       int k = cc - p; if (k == 0)            v = c1w[oc * 8 + h]; }
        else if (o < 750)  { int q = o - 384;  int oc = q / 61, p = q % 61; int k = cc - p; if (k >= 0 && k < 4)  v = c4w[oc * 32 + h * 4 + k]; }
        else if (o < 1044) { int q = o - 750;  int oc = q / 49, p = q % 49; int k = cc - p; if (k >= 0 && k < 16) v = c16w[oc * 128 + h * 16 + k]; }
        else if (o < 1242) { int q = o - 1044; int oc = q / 33, p = q % 33; int k = cc - p; if (k >= 0 && k < 32) v = c32w[oc * 256 + h * 32 + k]; }
        g_wc[j] = wmma::__float_to_tf32(v);
    } else if (idx < T5) {
        int o = idx - T4;
        float v = 0.f;
        if (o < 384)       v = c1b[o >> 6];
        else if (o < 750)  v = c4b[(o - 384) / 61];
        else if (o < 1044) v = c16b[(o - 750) / 49];
        else if (o < 1242) v = c32b[(o - 1044) / 33];
        g_cb[o] = v;
    }
}

// ---------------- graph prep: count + scan + scatter, single block ----------
__global__ void k_prep(const int* __restrict__ ei) {
    __shared__ int scnt[N_DIM];
    __shared__ int soff[1024];
    int t = threadIdx.x;                       // 1024 threads
    if (t < N_DIM) scnt[t] = 0;
    __syncthreads();
    for (int e = t; e < ME; e += 1024) atomicAdd(&scnt[edge_dst(ei, e)], 1);
    __syncthreads();
    soff[t] = (t < N_DIM) ? scnt[t] : 0;
    __syncthreads();
    for (int o = 1; o < 1024; o <<= 1) {
        int v = soff[t];
        int a = (t >= o) ? soff[t - o] : 0;
        __syncthreads();
        soff[t] = v + a;
        __syncthreads();
    }
    if (t < N_DIM) g_offset[t + 1] = soff[t];
    if (t == 0)    g_offset[0] = 0;
    if (t < N_DIM) scnt[t] = (t == 0) ? 0 : soff[t - 1];
    __syncthreads();
    for (int e = t; e < ME; e += 1024) {
        int d = edge_dst(ei, e);
        int pos = atomicAdd(&scnt[d], 1);
        g_csr[pos] = e;
    }
}

// ---------------- fused: h = feat@W, then xl/xr = h@W_l/W_r (8 nodes/block) --
__global__ void k_hx(const float* __restrict__ met, const float* __restrict__ dis,
                     const float* __restrict__ Wrna, const float* __restrict__ Wdis,
                     const float* __restrict__ Wl, const float* __restrict__ bl,
                     const float* __restrict__ Wr, const float* __restrict__ br) {
    __shared__ float srows[8][600];
    __shared__ float sh[8][C_DIM];
    int b = blockIdx.x;                  // 0..104 ; blocks 0..74 rna, 75..104 dis
    int tid = threadIdx.x;               // 512
    bool rna = (b < 75);
    int r0 = rna ? b * 8 : R_DIM + (b - 75) * 8;
    int K  = rna ? R_DIM : D_DIM;
    const float* src = rna ? met : dis;
    int lr0 = rna ? b * 8 : (b - 75) * 8;

    for (int i = tid; i < 8 * K; i += 512) {
        int g = i / K, k = i % K;
        srows[g][k] = src[(size_t)(lr0 + g) * K + k];
    }
    __syncthreads();

    {   // phase 1: h rows
        int g = tid >> 6, c = tid & 63;
        const float* W = rna ? Wrna : Wdis;
        float acc = 0.f;
        #pragma unroll 4
        for (int k = 0; k < K; k++) acc += srows[g][k] * W[k * C_DIM + c];
        sh[g][c] = acc;
    }
    __syncthreads();

    {   // phase 2: xl/xr for 8 nodes
        int j = tid;
        float al[8] = {0,0,0,0,0,0,0,0};
        float ar[8] = {0,0,0,0,0,0,0,0};
        #pragma unroll 4
        for (int k = 0; k < C_DIM; k++) {
            float wl = Wl[k * HC + j];
            float wr = Wr[k * HC + j];
            #pragma unroll
            for (int g = 0; g < 8; g++) {
                float hv = sh[g][k];
                al[g] += hv * wl;
                ar[g] += hv * wr;
            }
        }
        float bjl = bl[j], bjr = br[j];
        #pragma unroll
        for (int g = 0; g < 8; g++) {
            g_xl[(size_t)(r0 + g) * HC + j] = al[g] + bjl;
            g_xr[(size_t)(r0 + g) * HC + j] = ar[g] + bjr;
        }
    }
}

// ---------------- edge logits: one warp per edge, batched float4 loads -------
__global__ void k_logits(const int* __restrict__ ei, const float* __restrict__ att) {
    __shared__ float4 satt[128];
    int tid = threadIdx.x;                // 256
    if (tid < 128) satt[tid] = ((const float4*)att)[tid];
    __syncthreads();
    int e = (blockIdx.x * 256 + tid) >> 5;
    if (e >= ME) return;
    int lane = tid & 31;
    int src = edge_src(ei, e);
    int dst = edge_dst(ei, e);
    const float4* pl4 = (const float4*)(g_xl + (size_t)src * HC);
    const float4* pr4 = (const float4*)(g_xr + (size_t)dst * HC);

    float4 a[4], b[4];
    #pragma unroll
    for (int q = 0; q < 4; q++) { a[q] = pl4[lane + 32 * q]; b[q] = pr4[lane + 32 * q]; }

    int half = lane >> 4;
    #pragma unroll
    for (int q = 0; q < 4; q++) {
        float4 w = satt[lane + 32 * q];
        float vx = a[q].x + b[q].x; vx = vx > 0.f ? vx : NEG * vx;
        float vy = a[q].y + b[q].y; vy = vy > 0.f ? vy : NEG * vy;
        float vz = a[q].z + b[q].z; vz = vz > 0.f ? vz : NEG * vz;
        float vw = a[q].w + b[q].w; vw = vw > 0.f ? vw : NEG * vw;
        float t = vx * w.x + vy * w.y + vz * w.z + vw * w.w;
        #pragma unroll
        for (int o = 8; o > 0; o >>= 1) t += __shfl_xor_sync(0xffffffffu, t, o);
        if ((lane & 15) == 0) g_logits[e * H_DIM + 2 * q + half] = t;
    }
}

// ---------------- GAT softmax + aggregate only -------------------------------
__global__ void k_gatconv(const int* __restrict__ ei, const float* __restrict__ gb) {
    __shared__ float sm[H_DIM], sinv[H_DIM];
    __shared__ int   sedge[64], ssrc[64];
    __shared__ float salpha[8 * 64];
    int n = blockIdx.x;
    int tid = threadIdx.x;               // 256
    int h = tid >> 5, lane = tid & 31;

    int beg = g_offset[n], end = g_offset[n + 1], deg = end - beg;

    float m = -1e30f;
    for (int i = beg + lane; i < end; i += 32)
        m = fmaxf(m, g_logits[g_csr[i] * H_DIM + h]);
    #pragma unroll
    for (int o = 16; o > 0; o >>= 1) m = fmaxf(m, __shfl_xor_sync(0xffffffffu, m, o));
    float s = 0.f;
    for (int i = beg + lane; i < end; i += 32)
        s += __expf(g_logits[g_csr[i] * H_DIM + h] - m);
    #pragma unroll
    for (int o = 16; o > 0; o >>= 1) s += __shfl_xor_sync(0xffffffffu, s, o);
    if (lane == 0) { sm[h] = m; sinv[h] = 1.f / (s + 1e-16f); }
    __syncthreads();

    float2 acc = ((const float2*)gb)[tid];
    for (int c0 = 0; c0 < deg; c0 += 64) {
        int nch = min(64, deg - c0);
        if (tid < nch) {
            int e = g_csr[beg + c0 + tid];
            sedge[tid] = e;
            ssrc[tid] = edge_src(ei, e);
        }
        __syncthreads();
        {
            int i = tid & 63, hh = tid >> 6;
            if (i < nch) salpha[hh * 64 + i] =
                __expf(g_logits[sedge[i] * H_DIM + hh] - sm[hh]) * sinv[hh];
            i = (tid + 256) & 63; hh = (tid + 256) >> 6;
            if (i < nch) salpha[hh * 64 + i] =
                __expf(g_logits[sedge[i] * H_DIM + hh] - sm[hh]) * sinv[hh];
        }
        __syncthreads();
        for (int i = 0; i < nch; i++) {
            const float2* px = (const float2*)(g_xl + (size_t)ssrc[i] * HC);
            float a = salpha[h * 64 + i];      // warp-uniform
            float2 v = px[tid];
            acc.x += a * v.x;
            acc.y += a * v.y;
        }
        __syncthreads();
    }
    float2 o;
    o.x = wmma::__float_to_tf32(acc.x);
    o.y = wmma::__float_to_tf32(acc.y);
    ((float2*)(g_res + (size_t)n * HC))[tid] = o;
}

// ---------------- shared GEMM config (tf32 wmma + 3-stage cp.async) ----------
#define BM 128
#define BN 64
#define BK 32
#define LDA 36
#define LDB 68
#define STG (BM * LDA + BK * LDB)   // 4608 + 2176 = 6784 floats
#define FC_SMEM (3 * STG * 4)       // 81408 bytes (3 stages)

extern __shared__ float fcbuf[];

template<int NTI>
__device__ __forceinline__ void gemm_body(const float* __restrict__ Abase, int lda_g,
                                          const float* __restrict__ Bbase,
                                          int m0, int n0, int tid,
                                          wmma::fragment<wmma::accumulator, 16, 16, 8, float> (&acc)[2][2],
                                          int wm, int wn) {
    auto load_stage = [&](int s, int kt) {
        float* As = fcbuf + s * STG;
        float* Bs = As + BM * LDA;
        int k0 = kt * BK;
        #pragma unroll
        for (int t = 0; t < 4; t++) {          // A: 1024 float4
            int i = tid + t * 256;
            int r = i >> 3, c4 = i & 7;
            cp16(As + r * LDA + c4 * 4, Abase + (size_t)(m0 + r) * lda_g + k0 + c4 * 4);
        }
        #pragma unroll
        for (int t = 0; t < 2; t++) {          // B: 512 float4
            int i = tid + t * 256;
            int r = i >> 4, c4 = i & 15;
            cp16(Bs + r * LDB + c4 * 4, Bbase + (size_t)(k0 + r) * NP + n0 + c4 * 4);
        }
        cp_commit();
    };

    load_stage(0, 0);
    if (NTI > 1) load_stage(1, 1);
    for (int t = 0; t < NTI; t++) {
        if (t + 2 < NTI) { load_stage((t + 2) % 3, t + 2); cp_wait<2>(); }
        else if (t + 1 < NTI) cp_wait<1>();
        else cp_wait<0>();
        __syncthreads();
        const float* As = fcbuf + (t % 3) * STG;
        const float* Bs = As + BM * LDA;
        #pragma unroll
        for (int kk = 0; kk < BK; kk += 8) {
            wmma::fragment<wmma::matrix_a, 16, 16, 8, wmma::precision::tf32, wmma::row_major> a0, a1;
            wmma::fragment<wmma::matrix_b, 16, 16, 8, wmma::precision::tf32, wmma::row_major> b0, b1;
            wmma::load_matrix_sync(a0, As + (wm * 32) * LDA + kk, LDA);
            wmma::load_matrix_sync(a1, As + (wm * 32 + 16) * LDA + kk, LDA);
            wmma::load_matrix_sync(b0, Bs + kk * LDB + wn * 32, LDB);
            wmma::load_matrix_sync(b1, Bs + kk * LDB + wn * 32 + 16, LDB);
            wmma::mma_sync(acc[0][0], a0, b0, acc[0][0]);
            wmma::mma_sync(acc[0][1], a0, b1, acc[0][1]);
            wmma::mma_sync(acc[1][0], a1, b0, acc[1][0]);
            wmma::mma_sync(acc[1][1], a1, b1, acc[1][1]);
        }
        __syncthreads();
    }
}

// ---------------- conv GEMM: g_cat = relu(g_res @ g_wc + g_cb), tf32 out -----
#define NT2 16   // HC / BK

__global__ void k_cnv() {
    int tid = threadIdx.x;             // 256
    int warp = tid >> 5;
    int wm = warp >> 1;
    int wn = warp & 1;
    int m0 = blockIdx.y * BM;
    int n0 = blockIdx.x * BN;

    wmma::fragment<wmma::accumulator, 16, 16, 8, float> acc[2][2];
    #pragma unroll
    for (int i = 0; i < 2; i++)
        #pragma unroll
        for (int j = 0; j < 2; j++) wmma::fill_fragment(acc[i][j], 0.f);

    gemm_body<NT2>(g_res, HC, g_wc, m0, n0, tid, acc, wm, wn);

    float* Cs = fcbuf;                          // 128 x 68
    #pragma unroll
    for (int i = 0; i < 2; i++)
        #pragma unroll
        for (int j = 0; j < 2; j++)
            wmma::store_matrix_sync(Cs + (wm * 32 + i * 16) * LDB + wn * 32 + j * 16,
                                    acc[i][j], LDB, wmma::mem_row_major);
    __syncthreads();
    #pragma unroll
    for (int t = 0; t < 32; t++) {
        int i = tid + t * 256;
        int r = i >> 6, c = i & 63;
        int gr = m0 + r, gc = n0 + c;
        if (gr < N_DIM) {
            float v = Cs[r * LDB + c] + g_cb[gc];
            g_cat[(size_t)gr * NP + gc] = wmma::__float_to_tf32(fmaxf(v, 0.f));
        }
    }
}

// ---------------- FC GEMM: g_feat = relu(g_cat @ g_wp + bfc) -----------------
#define NT 39   // KP / BK

__global__ void k_fc(const float* __restrict__ bfc) {
    int tid = threadIdx.x;             // 256
    int warp = tid >> 5;
    int wm = warp >> 1;
    int wn = warp & 1;
    int m0 = blockIdx.y * BM;
    int n0 = blockIdx.x * BN;

    wmma::fragment<wmma::accumulator, 16, 16, 8, float> acc[2][2];
    #pragma unroll
    for (int i = 0; i < 2; i++)
        #pragma unroll
        for (int j = 0; j < 2; j++) wmma::fill_fragment(acc[i][j], 0.f);

    gemm_body<NT>(g_cat, NP, g_wp, m0, n0, tid, acc, wm, wn);

    float* Cs = fcbuf;                          // 128 x 68
    #pragma unroll
    for (int i = 0; i < 2; i++)
        #pragma unroll
        for (int j = 0; j < 2; j++)
            wmma::store_matrix_sync(Cs + (wm * 32 + i * 16) * LDB + wn * 32 + j * 16,
                                    acc[i][j], LDB, wmma::mem_row_major);
    __syncthreads();
    #pragma unroll
    for (int t = 0; t < 32; t++) {
        int i = tid + t * 256;
        int r = i >> 6, c = i & 63;
        int gr = m0 + r, gc = n0 + c;
        if (gr < N_DIM && gc < F_CNN) {
            float v = Cs[r * LDB + c] + bfc[gc];
            g_feat[(size_t)gr * F_CNN + gc] = v > 0.f ? v : 0.f;
        }
    }
}

// ---------------- pairs: 4x12 tiled outer product, smem row cache ------------
#define NF2 621   // 1242/2
#define TI 4
#define TJ 12
#define NROWS (TI + TJ)
#define PAIRS_SMEM (NROWS * NF2 * 8)   // 79488 bytes

extern __shared__ float2 prbuf[];      // [NROWS][NF2]

__global__ void k_pairs(float* __restrict__ out) {
    int tid = threadIdx.x;              // 640
    int i0 = blockIdx.x * TI;           // rna base (150 blocks)
    int j0 = blockIdx.y * TJ;           // dis base (20 blocks)

    for (int k = tid; k < NROWS * NF2; k += 640) {
        int r = k / NF2, c = k % NF2;
        int row = (r < TI) ? (i0 + r) : (R_DIM + j0 + (r - TI));
        prbuf[k] = ((const float2*)(g_feat + (size_t)row * F_CNN))[c];
    }
    __syncthreads();
    if (tid >= NF2) return;

    float2 rv[TI];
    #pragma unroll
    for (int ii = 0; ii < TI; ii++) rv[ii] = prbuf[ii * NF2 + tid];

    #pragma unroll
    for (int jj = 0; jj < TJ; jj++) {
        float2 dv = prbuf[(TI + jj) * NF2 + tid];
        #pragma unroll
        for (int ii = 0; ii < TI; ii++) {
            float2 o;
            o.x = rv[ii].x * dv.x;
            o.y = rv[ii].y * dv.y;
            __stcs((float2*)(out + (size_t)((i0 + ii) * D_DIM + j0 + jj) * F_CNN) + tid, o);
        }
    }
}

// ---------------- launch ------------------------------------------------------
extern "C" void kernel_launch(void* const* d_in, const int* in_sizes, int n_in,
                              void* d_out, int out_size) {
    const int*   ei   = (const int*)d_in[0];
    const float* met  = (const float*)d_in[1];
    const float* dis  = (const float*)d_in[2];
    const float* rel  = (const float*)d_in[3];
    const float* Wr   = (const float*)d_in[4];
    const float* Wd   = (const float*)d_in[5];
    const float* Wl   = (const float*)d_in[6];
    const float* bl   = (const float*)d_in[7];
    const float* Wrt  = (const float*)d_in[8];
    const float* br   = (const float*)d_in[9];
    const float* att  = (const float*)d_in[10];
    const float* gb   = (const float*)d_in[11];
    const float* c1w  = (const float*)d_in[12];
    const float* c1b  = (const float*)d_in[13];
    const float* c4w  = (const float*)d_in[14];
    const float* c4b  = (const float*)d_in[15];
    const float* c16w = (const float*)d_in[16];
    const float* c16b = (const float*)d_in[17];
    const float* c32w = (const float*)d_in[18];
    const float* c32b = (const float*)d_in[19];
    const float* Wfc  = (const float*)d_in[20];
    const float* bfc  = (const float*)d_in[21];
    float* out = (float*)d_out;

    static int smem_set = 0;
    if (!smem_set) {
        cudaFuncSetAttribute(k_fc,    cudaFuncAttributeMaxDynamicSharedMemorySize, FC_SMEM);
        cudaFuncSetAttribute(k_cnv,   cudaFuncAttributeMaxDynamicSharedMemorySize, FC_SMEM);
        cudaFuncSetAttribute(k_pairs, cudaFuncAttributeMaxDynamicSharedMemorySize, PAIRS_SMEM);
        smem_set = 1;
    }

    size_t labels_off = (size_t)out_size - (size_t)R_DIM * D_DIM;
    const int pad_total = KP * NP + (MP - N_DIM) * NP + R_DIM * D_DIM + HC * NP + NP;

    // order: ncu captures launch index 3 -> k_pad this round
    k_prep<<<1, 1024>>>(ei);
    k_hx<<<105, 512>>>(met, dis, Wr, Wd, Wl, bl, Wrt, br);
    k_logits<<<(ME * 32 + 255) / 256, 256>>>(ei, att);
    k_pad<<<(pad_total + 255) / 256, 256>>>(Wfc, rel, out, labels_off,
                                            c1w, c4w, c16w, c32w, c1b, c4b, c16b, c32b);
    k_gatconv<<<N_DIM, 256>>>(ei, gb);
    k_cnv<<<dim3(NP / BN, MP / BM), 256, FC_SMEM>>>();
    k_fc<<<dim3(NP / BN, MP / BM), 256, FC_SMEM>>>(bfc);
    k_pairs<<<dim3(R_DIM / TI, D_DIM / TJ), 640, PAIRS_SMEM>>>(out);
}

// round 11
// speedup vs baseline: 1.0603x; 1.0603x over previous
#include <cuda_runtime.h>
#include <cstdint>
#include <mma.h>

using namespace nvcuda;

#define R_DIM 600
#define D_DIM 240
#define N_DIM 840
#define H_DIM 8
#define C_DIM 64
#define HC 512
#define E_DIM 20000
#define ME 20840            // E + N (self loops)
#define F_CNN 1242
#define NEG 0.2f

// padded dims for guard-free GEMM pipelines
#define KP 1248             // 39 * 32
#define NP 1280             // 20 * 64
#define MP 896              // 7 * 128

// ---------------- scratch (device globals; no allocation allowed) ----------
__device__ float g_xl[N_DIM * HC];
__device__ float g_xr[N_DIM * HC];
__device__ float g_logits[ME * H_DIM];
__device__ int   g_offset[N_DIM + 1];
__device__ int   g_csr[ME];
__device__ float g_res[MP * HC];       // GAT output, tf32-rounded; rows 840+ stay 0
__device__ float g_wc[HC * NP];        // expanded conv weights, tf32
__device__ float g_cb[NP];             // expanded conv bias
__device__ float g_cat[MP * NP];       // conv output, padded, tf32-rounded
__device__ float g_wp[KP * NP];        // padded Wfc, tf32
__device__ float g_feat[N_DIM * F_CNN];

// ---------------- cp.async helpers -------------------------------------------
__device__ __forceinline__ void cp16(float* dst_smem, const float* src) {
    unsigned int d = (unsigned int)__cvta_generic_to_shared(dst_smem);
    asm volatile("cp.async.cg.shared.global [%0], [%1], 16;\n" :: "r"(d), "l"(src) : "memory");
}
__device__ __forceinline__ void cp_commit() {
    asm volatile("cp.async.commit_group;\n" ::: "memory");
}
template<int W> __device__ __forceinline__ void cp_wait() {
    asm volatile("cp.async.wait_group %0;\n" :: "n"(W) : "memory");
}

// ---------------- edge helpers ------------------------------------------------
__device__ __forceinline__ int edge_dst(const int* ei, int e) {
    return (e < E_DIM) ? ei[E_DIM + e] : (e - E_DIM);
}
__device__ __forceinline__ int edge_src(const int* ei, int e) {
    return (e < E_DIM) ? ei[e] : (e - E_DIM);
}

// ---------------- pad kernel: Wfc pad, g_cat row pad, labels, WC, cb ---------
__global__ void k_pad(const float* __restrict__ Wfc, const float* __restrict__ rel,
                      float* __restrict__ out, size_t labels_off,
                      const float* __restrict__ c1w, const float* __restrict__ c4w,
                      const float* __restrict__ c16w, const float* __restrict__ c32w,
                      const float* __restrict__ c1b, const float* __restrict__ c4b,
                      const float* __restrict__ c16b, const float* __restrict__ c32b) {
    int idx = blockIdx.x * 256 + threadIdx.x;
    const int T1 = KP * NP;
    const int T2 = T1 + (MP - N_DIM) * NP;
    const int T3 = T2 + R_DIM * D_DIM;
    const int T4 = T3 + HC * NP;
    const int T5 = T4 + NP;
    if (idx < T1) {
        int r = idx / NP, c = idx % NP;
        float v = (r < F_CNN && c < F_CNN) ? Wfc[(size_t)r * F_CNN + c] : 0.f;
        g_wp[idx] = wmma::__float_to_tf32(v);
    } else if (idx < T2) {
        g_cat[(size_t)N_DIM * NP + (idx - T1)] = 0.f;
    } else if (idx < T3) {
        int j = idx - T2;
        out[labels_off + j] = rel[j];
    } else if (idx < T4) {
        int j = idx - T3;
        int c = j / NP, o = j % NP;
        int h = c >> 6, cc = c & 63;
        float v = 0.f;
        if (o < 384)       { int oc = o >> 6, p = o & 63;       int k = cc - p; if (k == 0)            v = c1w[oc * 8 + h]; }
        else if (o < 750)  { int q = o - 384;  int oc = q / 61, p = q % 61; int k = cc - p; if (k >= 0 && k < 4)  v = c4w[oc * 32 + h * 4 + k]; }
        else if (o < 1044) { int q = o - 750;  int oc = q / 49, p = q % 49; int k = cc - p; if (k >= 0 && k < 16) v = c16w[oc * 128 + h * 16 + k]; }
        else if (o < 1242) { int q = o - 1044; int oc = q / 33, p = q % 33; int k = cc - p; if (k >= 0 && k < 32) v = c32w[oc * 256 + h * 32 + k]; }
        g_wc[j] = wmma::__float_to_tf32(v);
    } else if (idx < T5) {
        int o = idx - T4;
        float v = 0.f;
        if (o < 384)       v = c1b[o >> 6];
        else if (o < 750)  v = c4b[(o - 384) / 61];
        else if (o < 1044) v = c16b[(o - 750) / 49];
        else if (o < 1242) v = c32b[(o - 1044) / 33];
        g_cb[o] = v;
    }
}

// ---------------- graph prep: count + scan + scatter, single block ----------
__global__ void k_prep(const int* __restrict__ ei) {
    __shared__ int scnt[N_DIM];
    __shared__ int soff[1024];
    int t = threadIdx.x;                       // 1024 threads
    if (t < N_DIM) scnt[t] = 0;
    __syncthreads();
    for (int e = t; e < ME; e += 1024) atomicAdd(&scnt[edge_dst(ei, e)], 1);
    __syncthreads();
    soff[t] = (t < N_DIM) ? scnt[t] : 0;
    __syncthreads();
    for (int o = 1; o < 1024; o <<= 1) {
        int v = soff[t];
        int a = (t >= o) ? soff[t - o] : 0;
        __syncthreads();
        soff[t] = v + a;
        __syncthreads();
    }
    if (t < N_DIM) g_offset[t + 1] = soff[t];
    if (t == 0)    g_offset[0] = 0;
    if (t < N_DIM) scnt[t] = (t == 0) ? 0 : soff[t - 1];
    __syncthreads();
    for (int e = t; e < ME; e += 1024) {
        int d = edge_dst(ei, e);
        int pos = atomicAdd(&scnt[d], 1);
        g_csr[pos] = e;
    }
}

// ---------------- fused: h = feat@W, then xl/xr = h@W_l/W_r (8 nodes/block) --
__global__ void k_hx(const float* __restrict__ met, const float* __restrict__ dis,
                     const float* __restrict__ Wrna, const float* __restrict__ Wdis,
                     const float* __restrict__ Wl, const float* __restrict__ bl,
                     const float* __restrict__ Wr, const float* __restrict__ br) {
    __shared__ float srows[8][600];
    __shared__ float sh[8][C_DIM];
    int b = blockIdx.x;                  // 0..104 ; blocks 0..74 rna, 75..104 dis
    int tid = threadIdx.x;               // 512
    bool rna = (b < 75);
    int r0 = rna ? b * 8 : R_DIM + (b - 75) * 8;
    int K  = rna ? R_DIM : D_DIM;
    const float* src = rna ? met : dis;
    int lr0 = rna ? b * 8 : (b - 75) * 8;

    for (int i = tid; i < 8 * K; i += 512) {
        int g = i / K, k = i % K;
        srows[g][k] = src[(size_t)(lr0 + g) * K + k];
    }
    __syncthreads();

    {   // phase 1: h rows
        int g = tid >> 6, c = tid & 63;
        const float* W = rna ? Wrna : Wdis;
        float acc = 0.f;
        #pragma unroll 4
        for (int k = 0; k < K; k++) acc += srows[g][k] * W[k * C_DIM + c];
        sh[g][c] = acc;
    }
    __syncthreads();

    {   // phase 2: xl/xr for 8 nodes
        int j = tid;
        float al[8] = {0,0,0,0,0,0,0,0};
        float ar[8] = {0,0,0,0,0,0,0,0};
        #pragma unroll 4
        for (int k = 0; k < C_DIM; k++) {
            float wl = Wl[k * HC + j];
            float wr = Wr[k * HC + j];
            #pragma unroll
            for (int g = 0; g < 8; g++) {
                float hv = sh[g][k];
                al[g] += hv * wl;
                ar[g] += hv * wr;
            }
        }
        float bjl = bl[j], bjr = br[j];
        #pragma unroll
        for (int g = 0; g < 8; g++) {
            g_xl[(size_t)(r0 + g) * HC + j] = al[g] + bjl;
            g_xr[(size_t)(r0 + g) * HC + j] = ar[g] + bjr;
        }
    }
}

// ---------------- edge logits: one warp per edge, batched float4 loads -------
__global__ void k_logits(const int* __restrict__ ei, const float* __restrict__ att) {
    __shared__ float4 satt[128];
    int tid = threadIdx.x;                // 256
    if (tid < 128) satt[tid] = ((const float4*)att)[tid];
    __syncthreads();
    int e = (blockIdx.x * 256 + tid) >> 5;
    if (e >= ME) return;
    int lane = tid & 31;
    int src = edge_src(ei, e);
    int dst = edge_dst(ei, e);
    const float4* pl4 = (const float4*)(g_xl + (size_t)src * HC);
    const float4* pr4 = (const float4*)(g_xr + (size_t)dst * HC);

    float4 a[4], b[4];
    #pragma unroll
    for (int q = 0; q < 4; q++) { a[q] = pl4[lane + 32 * q]; b[q] = pr4[lane + 32 * q]; }

    int half = lane >> 4;
    #pragma unroll
    for (int q = 0; q < 4; q++) {
        float4 w = satt[lane + 32 * q];
        float vx = a[q].x + b[q].x; vx = vx > 0.f ? vx : NEG * vx;
        float vy = a[q].y + b[q].y; vy = vy > 0.f ? vy : NEG * vy;
        float vz = a[q].z + b[q].z; vz = vz > 0.f ? vz : NEG * vz;
        float vw = a[q].w + b[q].w; vw = vw > 0.f ? vw : NEG * vw;
        float t = vx * w.x + vy * w.y + vz * w.z + vw * w.w;
        #pragma unroll
        for (int o = 8; o > 0; o >>= 1) t += __shfl_xor_sync(0xffffffffu, t, o);
        if ((lane & 15) == 0) g_logits[e * H_DIM + 2 * q + half] = t;
    }
}

// ---------------- GAT softmax + aggregate only -------------------------------
__global__ void k_gatconv(const int* __restrict__ ei, const float* __restrict__ gb) {
    __shared__ float sm[H_DIM], sinv[H_DIM];
    __shared__ int   sedge[64], ssrc[64];
    __shared__ float salpha[8 * 64];
    int n = blockIdx.x;
    int tid = threadIdx.x;               // 256
    int h = tid >> 5, lane = tid & 31;

    int beg = g_offset[n], end = g_offset[n + 1], deg = end - beg;

    float m = -1e30f;
    for (int i = beg + lane; i < end; i += 32)
        m = fmaxf(m, g_logits[g_csr[i] * H_DIM + h]);
    #pragma unroll
    for (int o = 16; o > 0; o >>= 1) m = fmaxf(m, __shfl_xor_sync(0xffffffffu, m, o));
    float s = 0.f;
    for (int i = beg + lane; i < end; i += 32)
        s += __expf(g_logits[g_csr[i] * H_DIM + h] - m);
    #pragma unroll
    for (int o = 16; o > 0; o >>= 1) s += __shfl_xor_sync(0xffffffffu, s, o);
    if (lane == 0) { sm[h] = m; sinv[h] = 1.f / (s + 1e-16f); }
    __syncthreads();

    float2 acc = ((const float2*)gb)[tid];
    for (int c0 = 0; c0 < deg; c0 += 64) {
        int nch = min(64, deg - c0);
        if (tid < nch) {
            int e = g_csr[beg + c0 + tid];
            sedge[tid] = e;
            ssrc[tid] = edge_src(ei, e);
        }
        __syncthreads();
        {
            int i = tid & 63, hh = tid >> 6;
            if (i < nch) salpha[hh * 64 + i] =
                __expf(g_logits[sedge[i] * H_DIM + hh] - sm[hh]) * sinv[hh];
            i = (tid + 256) & 63; hh = (tid + 256) >> 6;
            if (i < nch) salpha[hh * 64 + i] =
                __expf(g_logits[sedge[i] * H_DIM + hh] - sm[hh]) * sinv[hh];
        }
        __syncthreads();
        for (int i = 0; i < nch; i++) {
            const float2* px = (const float2*)(g_xl + (size_t)ssrc[i] * HC);
            float a = salpha[h * 64 + i];      // warp-uniform
            float2 v = px[tid];
            acc.x += a * v.x;
            acc.y += a * v.y;
        }
        __syncthreads();
    }
    float2 o;
    o.x = wmma::__float_to_tf32(acc.x);
    o.y = wmma::__float_to_tf32(acc.y);
    ((float2*)(g_res + (size_t)n * HC))[tid] = o;
}

// ---------------- shared GEMM config (tf32 wmma, 3-stage, 1 sync/iter) -------
#define BM 128
#define BN 64
#define BK 32
#define LDA 36
#define LDB 68
#define STG (BM * LDA + BK * LDB)   // 4608 + 2176 = 6784 floats
#define FC_SMEM (3 * STG * 4)       // 81408 bytes (3 stages)

extern __shared__ float fcbuf[];

template<int NTI>
__device__ __forceinline__ void gemm_body(const float* __restrict__ Abase, int lda_g,
                                          const float* __restrict__ Bbase,
                                          int m0, int n0, int tid,
                                          wmma::fragment<wmma::accumulator, 16, 16, 8, float> (&acc)[2][2],
                                          int wm, int wn) {
    auto load_stage = [&](int s, int kt) {
        float* As = fcbuf + s * STG;
        float* Bs = As + BM * LDA;
        int k0 = kt * BK;
        #pragma unroll
        for (int t = 0; t < 4; t++) {          // A: 1024 float4
            int i = tid + t * 256;
            int r = i >> 3, c4 = i & 7;
            cp16(As + r * LDA + c4 * 4, Abase + (size_t)(m0 + r) * lda_g + k0 + c4 * 4);
        }
        #pragma unroll
        for (int t = 0; t < 2; t++) {          // B: 512 float4
            int i = tid + t * 256;
            int r = i >> 4, c4 = i & 15;
            cp16(Bs + r * LDB + c4 * 4, Bbase + (size_t)(k0 + r) * NP + n0 + c4 * 4);
        }
        cp_commit();
    };

    // 3-stage ring, ONE barrier per iteration.
    // After the iter-t barrier every warp reads stage t%3; the new load targets
    // (t+2)%3 which can never alias t%3 or (t-? ) for warps at most 0 iters behind.
    load_stage(0, 0);
    if (NTI > 1) load_stage(1, 1);
    for (int t = 0; t < NTI; t++) {
        if (t + 1 < NTI) cp_wait<1>(); else cp_wait<0>();
        __syncthreads();
        if (t + 2 < NTI) load_stage((t + 2) % 3, t + 2);
        const float* As = fcbuf + (t % 3) * STG;
        const float* Bs = As + BM * LDA;
        #pragma unroll
        for (int kk = 0; kk < BK; kk += 8) {
            wmma::fragment<wmma::matrix_a, 16, 16, 8, wmma::precision::tf32, wmma::row_major> a0, a1;
            wmma::fragment<wmma::matrix_b, 16, 16, 8, wmma::precision::tf32, wmma::row_major> b0, b1;
            wmma::load_matrix_sync(a0, As + (wm * 32) * LDA + kk, LDA);
            wmma::load_matrix_sync(a1, As + (wm * 32 + 16) * LDA + kk, LDA);
            wmma::load_matrix_sync(b0, Bs + kk * LDB + wn * 32, LDB);
            wmma::load_matrix_sync(b1, Bs + kk * LDB + wn * 32 + 16, LDB);
            wmma::mma_sync(acc[0][0], a0, b0, acc[0][0]);
            wmma::mma_sync(acc[0][1], a0, b1, acc[0][1]);
            wmma::mma_sync(acc[1][0], a1, b0, acc[1][0]);
            wmma::mma_sync(acc[1][1], a1, b1, acc[1][1]);
        }
    }
    __syncthreads();   // before epilogue reuses stage-0 smem
}

// ---------------- conv GEMM: g_cat = relu(g_res @ g_wc + g_cb), tf32 out -----
#define NT2 16   // HC / BK

__global__ void k_cnv() {
    int tid = threadIdx.x;             // 256
    int warp = tid >> 5;
    int wm = warp >> 1;
    int wn = warp & 1;
    int m0 = blockIdx.y * BM;
    int n0 = blockIdx.x * BN;

    wmma::fragment<wmma::accumulator, 16, 16, 8, float> acc[2][2];
    #pragma unroll
    for (int i = 0; i < 2; i++)
        #pragma unroll
        for (int j = 0; j < 2; j++) wmma::fill_fragment(acc[i][j], 0.f);

    gemm_body<NT2>(g_res, HC, g_wc, m0, n0, tid, acc, wm, wn);

    float* Cs = fcbuf;                          // 128 x 68
    #pragma unroll
    for (int i = 0; i < 2; i++)
        #pragma unroll
        for (int j = 0; j < 2; j++)
            wmma::store_matrix_sync(Cs + (wm * 32 + i * 16) * LDB + wn * 32 + j * 16,
                                    acc[i][j], LDB, wmma::mem_row_major);
    __syncthreads();
    #pragma unroll
    for (int t = 0; t < 32; t++) {
        int i = tid + t * 256;
        int r = i >> 6, c = i & 63;
        int gr = m0 + r, gc = n0 + c;
        if (gr < N_DIM) {
            float v = Cs[r * LDB + c] + g_cb[gc];
            g_cat[(size_t)gr * NP + gc] = wmma::__float_to_tf32(fmaxf(v, 0.f));
        }
    }
}

// ---------------- FC GEMM: g_feat = relu(g_cat @ g_wp + bfc) -----------------
#define NT 39   // KP / BK

__global__ void k_fc(const float* __restrict__ bfc) {
    int tid = threadIdx.x;             // 256
    int warp = tid >> 5;
    int wm = warp >> 1;
    int wn = warp & 1;
    int m0 = blockIdx.y * BM;
    int n0 = blockIdx.x * BN;

    wmma::fragment<wmma::accumulator, 16, 16, 8, float> acc[2][2];
    #pragma unroll
    for (int i = 0; i < 2; i++)
        #pragma unroll
        for (int j = 0; j < 2; j++) wmma::fill_fragment(acc[i][j], 0.f);

    gemm_body<NT>(g_cat, NP, g_wp, m0, n0, tid, acc, wm, wn);

    float* Cs = fcbuf;                          // 128 x 68
    #pragma unroll
    for (int i = 0; i < 2; i++)
        #pragma unroll
        for (int j = 0; j < 2; j++)
            wmma::store_matrix_sync(Cs + (wm * 32 + i * 16) * LDB + wn * 32 + j * 16,
                                    acc[i][j], LDB, wmma::mem_row_major);
    __syncthreads();
    #pragma unroll
    for (int t = 0; t < 32; t++) {
        int i = tid + t * 256;
        int r = i >> 6, c = i & 63;
        int gr = m0 + r, gc = n0 + c;
        if (gr < N_DIM && gc < F_CNN) {
            float v = Cs[r * LDB + c] + bfc[gc];
            g_feat[(size_t)gr * F_CNN + gc] = v > 0.f ? v : 0.f;
        }
    }
}

// ---------------- pairs: 4x12 tiled outer product, smem row cache ------------
#define NF2 621   // 1242/2
#define TI 4
#define TJ 12
#define NROWS (TI + TJ)
#define PAIRS_SMEM (NROWS * NF2 * 8)   // 79488 bytes

extern __shared__ float2 prbuf[];      // [NROWS][NF2]

__global__ void k_pairs(float* __restrict__ out) {
    int tid = threadIdx.x;              // 640
    int i0 = blockIdx.x * TI;           // rna base (150 blocks)
    int j0 = blockIdx.y * TJ;           // dis base (20 blocks)

    for (int k = tid; k < NROWS * NF2; k += 640) {
        int r = k / NF2, c = k % NF2;
        int row = (r < TI) ? (i0 + r) : (R_DIM + j0 + (r - TI));
        prbuf[k] = ((const float2*)(g_feat + (size_t)row * F_CNN))[c];
    }
    __syncthreads();
    if (tid >= NF2) return;

    float2 rv[TI];
    #pragma unroll
    for (int ii = 0; ii < TI; ii++) rv[ii] = prbuf[ii * NF2 + tid];

    #pragma unroll
    for (int jj = 0; jj < TJ; jj++) {
        float2 dv = prbuf[(TI + jj) * NF2 + tid];
        #pragma unroll
        for (int ii = 0; ii < TI; ii++) {
            float2 o;
            o.x = rv[ii].x * dv.x;
            o.y = rv[ii].y * dv.y;
            __stcs((float2*)(out + (size_t)((i0 + ii) * D_DIM + j0 + jj) * F_CNN) + tid, o);
        }
    }
}

// ---------------- launch ------------------------------------------------------
extern "C" void kernel_launch(void* const* d_in, const int* in_sizes, int n_in,
                              void* d_out, int out_size) {
    const int*   ei   = (const int*)d_in[0];
    const float* met  = (const float*)d_in[1];
    const float* dis  = (const float*)d_in[2];
    const float* rel  = (const float*)d_in[3];
    const float* Wr   = (const float*)d_in[4];
    const float* Wd   = (const float*)d_in[5];
    const float* Wl   = (const float*)d_in[6];
    const float* bl   = (const float*)d_in[7];
    const float* Wrt  = (const float*)d_in[8];
    const float* br   = (const float*)d_in[9];
    const float* att  = (const float*)d_in[10];
    const float* gb   = (const float*)d_in[11];
    const float* c1w  = (const float*)d_in[12];
    const float* c1b  = (const float*)d_in[13];
    const float* c4w  = (const float*)d_in[14];
    const float* c4b  = (const float*)d_in[15];
    const float* c16w = (const float*)d_in[16];
    const float* c16b = (const float*)d_in[17];
    const float* c32w = (const float*)d_in[18];
    const float* c32b = (const float*)d_in[19];
    const float* Wfc  = (const float*)d_in[20];
    const float* bfc  = (const float*)d_in[21];
    float* out = (float*)d_out;

    static int inited = 0;
    static cudaStream_t s1, s2;
    static cudaEvent_t e0, e1, e2;
    if (!inited) {
        cudaFuncSetAttribute(k_fc,    cudaFuncAttributeMaxDynamicSharedMemorySize, FC_SMEM);
        cudaFuncSetAttribute(k_cnv,   cudaFuncAttributeMaxDynamicSharedMemorySize, FC_SMEM);
        cudaFuncSetAttribute(k_pairs, cudaFuncAttributeMaxDynamicSharedMemorySize, PAIRS_SMEM);
        cudaStreamCreateWithFlags(&s1, cudaStreamNonBlocking);
        cudaStreamCreateWithFlags(&s2, cudaStreamNonBlocking);
        cudaEventCreateWithFlags(&e0, cudaEventDisableTiming);
        cudaEventCreateWithFlags(&e1, cudaEventDisableTiming);
        cudaEventCreateWithFlags(&e2, cudaEventDisableTiming);
        inited = 1;
    }

    size_t labels_off = (size_t)out_size - (size_t)R_DIM * D_DIM;
    const int pad_total = KP * NP + (MP - N_DIM) * NP + R_DIM * D_DIM + HC * NP + NP;

    // fork: prep (s1) and pad (s2) run concurrently with hx->logits (main)
    cudaEventRecord(e0, 0);
    cudaStreamWaitEvent(s1, e0, 0);
    cudaStreamWaitEvent(s2, e0, 0);
    k_prep<<<1, 1024, 0, s1>>>(ei);
    cudaEventRecord(e1, s1);
    k_pad<<<(pad_total + 255) / 256, 256, 0, s2>>>(Wfc, rel, out, labels_off,
                                                   c1w, c4w, c16w, c32w, c1b, c4b, c16b, c32b);
    cudaEventRecord(e2, s2);

    k_hx<<<105, 512>>>(met, dis, Wr, Wd, Wl, bl, Wrt, br);
    k_logits<<<(ME * 32 + 255) / 256, 256>>>(ei, att);
    cudaStreamWaitEvent(0, e1, 0);                 // gatconv needs CSR
    k_gatconv<<<N_DIM, 256>>>(ei, gb);
    cudaStreamWaitEvent(0, e2, 0);                 // cnv needs g_wc/g_cb
    k_cnv<<<dim3(NP / BN, MP / BM), 256, FC_SMEM>>>();
    k_fc<<<dim3(NP / BN, MP / BM), 256, FC_SMEM>>>(bfc);
    k_pairs<<<dim3(R_DIM / TI, D_DIM / TJ), 640, PAIRS_SMEM>>>(out);
}